// round 15
// baseline (speedup 1.0000x reference)
#include <cuda_runtime.h>
#include <cuda_bf16.h>
#include <mma.h>
#include <cstdint>

using namespace nvcuda;

// Problem constants (fixed by setup_inputs)
#define NN 100000   // nodes
#define EE 1000000  // edges
#define DD 64       // input dim
#define HH 128      // embed_dim
#define KK 128      // 2*DD
#define ELL 64      // ELL row stride (max degree ~41 for Poisson(20))

typedef unsigned int u32;

// ---------------- scratch (no allocations allowed) ----------------
// g_cnt starts zero at module load; the fused gemm resets it (row-indexed,
// full [0,N) coverage) every run, so k_fillprep can rely on it being zero.
__device__ int g_cnt[NN];            // degree counters (slot allocator; self-resetting)
__device__ int g_adj[NN * ELL];      // ELL adjacency
__device__ u32 g_fhi[NN * 32];       // features split hi, bf16x2 pairs [N][32]
__device__ u32 g_flo[NN * 32];       // features split lo
__device__ __nv_bfloat16 g_Whi[HH * KK];   // W split hi, row-major [h][k]
__device__ __nv_bfloat16 g_Wlo[HH * KK];   // W split lo

// ---------------- helpers ----------------
// split floats into bf16 hi + bf16 lo, packed pairwise
__device__ __forceinline__ void cvt2_split(float a, float b, u32& hi, u32& lo) {
    __nv_bfloat162 h2 = __floats2bfloat162_rn(a, b);
    float ra = a - __bfloat162float(h2.x);
    float rb = b - __bfloat162float(h2.y);
    __nv_bfloat162 l2 = __floats2bfloat162_rn(ra, rb);
    hi = *reinterpret_cast<u32*>(&h2);
    lo = *reinterpret_cast<u32*>(&l2);
}

// ---------------- kernel 1: fused ELL fill + split W + split features ----------
// Block-range partition: blocks [0, fill_blocks) do the edge fill (atomic slot
// allocation); remaining blocks do the DRAM-streaming splits. No dependency,
// complementary bottlenecks -> they overlap across SMs.
__global__ void k_fillprep(const int* __restrict__ ei,
                           const float2* __restrict__ feat2,
                           const float* __restrict__ W,
                           int n_edges, int n_nodes, int fill_blocks) {
    if ((int)blockIdx.x < fill_blocks) {
        int e = blockIdx.x * blockDim.x + threadIdx.x;
        if (e >= n_edges) return;
        int s = ei[e];
        int d = ei[n_edges + e];
        int p0 = atomicAdd(&g_cnt[s], 1);
        g_adj[s * ELL + p0] = d;
        int p1 = atomicAdd(&g_cnt[d], 1);
        g_adj[d * ELL + p1] = s;
    } else {
        int gid = (blockIdx.x - fill_blocks) * blockDim.x + threadIdx.x;
        if (gid < HH * KK) {
            float w = W[gid];
            __nv_bfloat16 hb = __float2bfloat16_rn(w);
            float r = w - __bfloat162float(hb);
            g_Whi[gid] = hb;
            g_Wlo[gid] = __float2bfloat16_rn(r);
        }
        if (gid < n_nodes * 32) {
            float2 f = feat2[gid];
            u32 hi, lo;
            cvt2_split(f.x, f.y, hi, lo);
            g_fhi[gid] = hi;
            g_flo[gid] = lo;
        }
    }
}

// ---------------- kernel 2: FUSED gather + wmma GEMM (3xBF16 split) ----------
// BM=64 rows/block, 128 threads (4 warps), warp tile 32x64 (2x4 fragments).
// Gather phase: each warp computes neighbor means for 16 of the block's rows
// (fp32 accumulate over ELL adjacency) and writes split bf16 directly into the
// smem A tiles. Cross-CTA overlap (2 CTAs/SM) hides gather latency under the
// other CTA's MMA. Then the standard 3-pass split MMA + reg epilogue.
#define BM 64
#define ASTRIDE 136
#define A_ELEMS (BM * ASTRIDE)                // 8704 bf16 (17408 B)
#define B_ELEMS (128 * ASTRIDE)               // 17408 bf16 (34816 B)
#define BIAS_OFF (2 * A_ELEMS + 2 * B_ELEMS)  // bf16-element offset of bias block
#define SMEM_DYN (BIAS_OFF * 2 + 16 * HH * 4) // 104448 + 8192 = 112640 bytes

__global__ __launch_bounds__(128)
void gemm_kernel(const int* __restrict__ nodes,
                 const float2* __restrict__ feat2,
                 const float* __restrict__ bias,
                 float* __restrict__ out,
                 int n_rows, int n_nodes) {
    extern __shared__ __nv_bfloat16 smem[];
    __nv_bfloat16* Ahi = smem;
    __nv_bfloat16* Alo = smem + A_ELEMS;
    __nv_bfloat16* Bhi = smem + 2 * A_ELEMS;
    __nv_bfloat16* Blo = smem + 2 * A_ELEMS + B_ELEMS;
    float* biasf = (float*)(smem + BIAS_OFF);   // 16 rows x 128 cols replicated

    int tid = threadIdx.x;
    int wid = tid >> 5;
    int lane = tid & 31;
    int block_m = blockIdx.x * BM;

    // ---- stage B = W hi & lo, col-major: Bs[k + h*ASTRIDE] ----
    {
        const uint4* shi = (const uint4*)g_Whi;
        const uint4* slo = (const uint4*)g_Wlo;
        #pragma unroll
        for (int i = 0; i < (HH * KK / 8) / 128; ++i) {
            int idx = tid + i * 128;          // octet index
            int h = idx >> 4;                 // 16 octets per h
            int k = (idx & 15) * 8;
            *(uint4*)&Bhi[k + h * ASTRIDE] = shi[idx];
            *(uint4*)&Blo[k + h * ASTRIDE] = slo[idx];
        }
    }

    // ---- stage self-features (cols 0..63): pure uint4 copies ----
    // 2 threads per row, each copies 4 octets of hi and lo.
    {
        int r = tid >> 1;
        int qbase = (tid & 1) * 4;
        int row = block_m + r;
        bool valid = row < n_rows;
        int g = valid ? nodes[row] : 0;
        const uint4* shi = (const uint4*)&g_fhi[(size_t)g * 32];
        const uint4* slo = (const uint4*)&g_flo[(size_t)g * 32];
        uint4 z = make_uint4(0, 0, 0, 0);
        #pragma unroll
        for (int qi = 0; qi < 4; ++qi) {
            int q = qbase + qi;
            *(uint4*)&Ahi[r * ASTRIDE + q * 8] = valid ? shi[q] : z;
            *(uint4*)&Alo[r * ASTRIDE + q * 8] = valid ? slo[q] : z;
        }
    }

    // ---- fill replicated bias block (16 identical rows) ----
    #pragma unroll
    for (int i = 0; i < 16; ++i) {
        int idx = tid + i * 128;              // 2048 entries
        biasf[idx] = bias[idx & (HH - 1)];
    }

    // ---- GATHER phase: warp computes means for 16 rows, writes cols 64..127 ----
    // lane owns feature pair (2*lane, 2*lane+1); fp32 accumulate, then split.
    for (int rr = 0; rr < 16; ++rr) {
        int r = wid * 16 + rr;                // local row 0..63
        int row = block_m + r;
        float2 acc = make_float2(0.f, 0.f);
        if (row < n_rows) {
            int g = nodes[row];               // lane-uniform -> broadcast
            int deg = g_cnt[g];
            const int* adj = &g_adj[g * ELL]; // 256B aligned
            int j = 0;
            for (; j + 4 <= deg; j += 4) {
                int4 i4 = *(const int4*)&adj[j];
                float2 a = feat2[(size_t)i4.x * 32 + lane];
                float2 b = feat2[(size_t)i4.y * 32 + lane];
                float2 c = feat2[(size_t)i4.z * 32 + lane];
                float2 d = feat2[(size_t)i4.w * 32 + lane];
                acc.x += a.x + b.x + c.x + d.x;
                acc.y += a.y + b.y + c.y + d.y;
            }
            for (; j < deg; ++j) {
                float2 a = feat2[(size_t)adj[j] * 32 + lane];
                acc.x += a.x;
                acc.y += a.y;
            }
            float inv = 1.0f / fmaxf((float)deg, 1.0f);
            acc.x *= inv;
            acc.y *= inv;
        }
        u32 hi, lo;
        cvt2_split(acc.x, acc.y, hi, lo);
        *(u32*)&Ahi[r * ASTRIDE + 64 + lane * 2] = hi;
        *(u32*)&Alo[r * ASTRIDE + 64 + lane * 2] = lo;
    }
    __syncthreads();

    // re-arm counters for the next replay (row-indexed: full [0,N) coverage).
    // Placed after the sync so every warp's gather reads finished.
    if (tid < BM) {
        int row = block_m + tid;
        if (row < n_nodes) g_cnt[row] = 0;
    }

    // ---- wmma: 4 warps in 2x2 grid, warp tile 32x64 (2x4 frags) ----
    int wm = wid & 1;      // rows wm*32
    int wn = wid >> 1;     // cols wn*64

    wmma::fragment<wmma::accumulator, 16, 16, 16, float> acc[2][4];
    #pragma unroll
    for (int i = 0; i < 2; ++i)
        #pragma unroll
        for (int j = 0; j < 4; ++j) wmma::fill_fragment(acc[i][j], 0.0f);

    const __nv_bfloat16* Aptr[3] = {Ahi, Ahi, Alo};
    const __nv_bfloat16* Bptr[3] = {Bhi, Blo, Bhi};

    #pragma unroll
    for (int pass = 0; pass < 3; ++pass) {
        const __nv_bfloat16* As = Aptr[pass];
        const __nv_bfloat16* Bs = Bptr[pass];
        #pragma unroll
        for (int k0 = 0; k0 < KK; k0 += 16) {
            wmma::fragment<wmma::matrix_a, 16, 16, 16, __nv_bfloat16, wmma::row_major> af[2];
            wmma::fragment<wmma::matrix_b, 16, 16, 16, __nv_bfloat16, wmma::col_major> bf[4];
            #pragma unroll
            for (int i = 0; i < 2; ++i)
                wmma::load_matrix_sync(af[i], As + (wm * 32 + i * 16) * ASTRIDE + k0, ASTRIDE);
            #pragma unroll
            for (int j = 0; j < 4; ++j)
                wmma::load_matrix_sync(bf[j], Bs + k0 + (wn * 64 + j * 16) * ASTRIDE, ASTRIDE);
            #pragma unroll
            for (int i = 0; i < 2; ++i)
                #pragma unroll
                for (int j = 0; j < 4; ++j)
                    wmma::mma_sync(acc[i][j], af[i], bf[j], acc[i][j]);
        }
    }

    // ---- epilogue ----
    if (block_m + BM <= n_rows) {
        // full tile: bias+relu in registers, direct fragment store to gmem
        wmma::fragment<wmma::accumulator, 16, 16, 16, float> bfr[4];
        #pragma unroll
        for (int j = 0; j < 4; ++j)
            wmma::load_matrix_sync(bfr[j], biasf + wn * 64 + j * 16, HH,
                                   wmma::mem_row_major);
        #pragma unroll
        for (int i = 0; i < 2; ++i)
            #pragma unroll
            for (int j = 0; j < 4; ++j) {
                #pragma unroll
                for (int t = 0; t < acc[i][j].num_elements; ++t)
                    acc[i][j].x[t] = fmaxf(acc[i][j].x[t] + bfr[j].x[t], 0.f);
                wmma::store_matrix_sync(
                    out + (size_t)(block_m + wm * 32 + i * 16) * HH + wn * 64 + j * 16,
                    acc[i][j], HH, wmma::mem_row_major);
            }
    } else {
        // partial tail block: stage through smem with per-row guards
        __syncthreads();   // tiles no longer needed
        float* stage = (float*)smem;                   // 4 warps x 32x64 f32 = 32KB
        float* wstage = stage + wid * (32 * 64);
        #pragma unroll
        for (int i = 0; i < 2; ++i)
            #pragma unroll
            for (int j = 0; j < 4; ++j)
                wmma::store_matrix_sync(wstage + i * 16 * 64 + j * 16, acc[i][j],
                                        64, wmma::mem_row_major);
        __syncwarp();
        int row = block_m + wm * 32 + lane;
        if (row < n_rows) {
            const float* srow = wstage + lane * 64;
            float* orow = out + (size_t)row * HH + wn * 64;
            #pragma unroll
            for (int c = 0; c < 64; c += 4) {
                float4 o;
                o.x = fmaxf(srow[c + 0] + bias[wn * 64 + c + 0], 0.f);
                o.y = fmaxf(srow[c + 1] + bias[wn * 64 + c + 1], 0.f);
                o.z = fmaxf(srow[c + 2] + bias[wn * 64 + c + 2], 0.f);
                o.w = fmaxf(srow[c + 3] + bias[wn * 64 + c + 3], 0.f);
                *(float4*)&orow[c] = o;
            }
        }
    }
}

// ---------------- launch ----------------
extern "C" void kernel_launch(void* const* d_in, const int* in_sizes, int n_in,
                              void* d_out, int out_size) {
    const int*    nodes    = (const int*)d_in[0];
    const float*  features = (const float*)d_in[1];
    const int*    ei       = (const int*)d_in[2];
    const float*  W        = (const float*)d_in[3];
    const float*  bias     = (const float*)d_in[4];
    float*        out      = (float*)d_out;

    int n_rows  = in_sizes[0];           // B == N
    int n_nodes = in_sizes[1] / DD;      // N
    int n_edges = in_sizes[2] / 2;       // E

    const float2* feat2 = (const float2*)features;

    // opt-in to >48KB dynamic smem (immediate host-side call, idempotent)
    cudaFuncSetAttribute(gemm_kernel,
                         cudaFuncAttributeMaxDynamicSharedMemorySize, SMEM_DYN);

    // 1. fused: ELL fill (blocks [0,fb)) + split W/features (remaining blocks)
    {
        int fb = (n_edges + 255) / 256;
        int pb = (n_nodes * 32 + 255) / 256;
        k_fillprep<<<fb + pb, 256>>>(ei, feat2, W, n_edges, n_nodes, fb);
    }
    // 2. fused gather + wmma GEMM (re-arms g_cnt)
    {
        int blocks = (n_rows + BM - 1) / BM;
        gemm_kernel<<<blocks, 128, SMEM_DYN>>>(nodes, feat2, bias, out,
                                               n_rows, n_nodes);
    }
}

// round 16
// speedup vs baseline: 1.9172x; 1.9172x over previous
#include <cuda_runtime.h>
#include <cuda_bf16.h>
#include <mma.h>
#include <cstdint>

using namespace nvcuda;

// Problem constants (fixed by setup_inputs)
#define NN 100000   // nodes
#define EE 1000000  // edges
#define DD 64       // input dim
#define HH 128      // embed_dim
#define KK 128      // 2*DD
#define ELL 64      // ELL row stride (max degree ~41 for Poisson(20))

typedef unsigned int u32;

// ---------------- scratch (no allocations allowed) ----------------
// g_cnt starts zero at module load; k_gather resets it to zero every run,
// so k_fillprep can rely on it being zero without a separate zeroing pass.
__device__ int g_cnt[NN];            // degree counters (slot allocator; self-resetting)
__device__ int g_adj[NN * ELL];      // ELL adjacency
__device__ u32 g_fhi[NN * 32];       // features split hi, bf16x2 pairs [N][32]
__device__ u32 g_flo[NN * 32];       // features split lo
__device__ u32 g_mhi[NN * 32];       // neighbor means split hi
__device__ u32 g_mlo[NN * 32];       // neighbor means split lo
__device__ __nv_bfloat16 g_Whi[HH * KK];   // W split hi, row-major [h][k]
__device__ __nv_bfloat16 g_Wlo[HH * KK];   // W split lo

// ---------------- helpers ----------------
// split floats into bf16 hi + bf16 lo, packed pairwise
__device__ __forceinline__ void cvt2_split(float a, float b, u32& hi, u32& lo) {
    __nv_bfloat162 h2 = __floats2bfloat162_rn(a, b);
    float ra = a - __bfloat162float(h2.x);
    float rb = b - __bfloat162float(h2.y);
    __nv_bfloat162 l2 = __floats2bfloat162_rn(ra, rb);
    hi = *reinterpret_cast<u32*>(&h2);
    lo = *reinterpret_cast<u32*>(&l2);
}

// ---------------- kernel 1: fused ELL fill + split W + split features ----------
// Block-range partition: blocks [0, fill_blocks) do the edge fill (atomic slot
// allocation); remaining blocks do the DRAM-streaming splits. No dependency,
// complementary bottlenecks -> they overlap across SMs.
__global__ void k_fillprep(const int* __restrict__ ei,
                           const float2* __restrict__ feat2,
                           const float* __restrict__ W,
                           int n_edges, int n_nodes, int fill_blocks) {
    if ((int)blockIdx.x < fill_blocks) {
        int e = blockIdx.x * blockDim.x + threadIdx.x;
        if (e >= n_edges) return;
        int s = ei[e];
        int d = ei[n_edges + e];
        int p0 = atomicAdd(&g_cnt[s], 1);
        g_adj[s * ELL + p0] = d;
        int p1 = atomicAdd(&g_cnt[d], 1);
        g_adj[d * ELL + p1] = s;
    } else {
        int gid = (blockIdx.x - fill_blocks) * blockDim.x + threadIdx.x;
        if (gid < HH * KK) {
            float w = W[gid];
            __nv_bfloat16 hb = __float2bfloat16_rn(w);
            float r = w - __bfloat162float(hb);
            g_Whi[gid] = hb;
            g_Wlo[gid] = __float2bfloat16_rn(r);
        }
        if (gid < n_nodes * 32) {
            float2 f = feat2[gid];
            u32 hi, lo;
            cvt2_split(f.x, f.y, hi, lo);
            g_fhi[gid] = hi;
            g_flo[gid] = lo;
        }
    }
}

// ---------------- kernel 2: gather-reduce: warp per node, writes split MEAN ----
// Also resets g_cnt[w] = 0, restoring the invariant the next run's fill needs.
__global__ __launch_bounds__(256)
void k_gather(const float2* __restrict__ feat2, int n_nodes) {
    int w = (blockIdx.x * blockDim.x + threadIdx.x) >> 5;
    if (w >= n_nodes) return;
    int lane = threadIdx.x & 31;
    int deg = g_cnt[w];
    const int* row = &g_adj[w * ELL];     // 256B aligned

    float2 acc = make_float2(0.f, 0.f);
    int j = 0;
    for (; j + 4 <= deg; j += 4) {
        int4 i4 = *(const int4*)&row[j];  // one LDG.128 for 4 indices
        float2 a = feat2[(size_t)i4.x * 32 + lane];
        float2 b = feat2[(size_t)i4.y * 32 + lane];
        float2 c = feat2[(size_t)i4.z * 32 + lane];
        float2 d = feat2[(size_t)i4.w * 32 + lane];
        acc.x += a.x + b.x + c.x + d.x;
        acc.y += a.y + b.y + c.y + d.y;
    }
    for (; j < deg; ++j) {
        float2 a = feat2[(size_t)row[j] * 32 + lane];
        acc.x += a.x;
        acc.y += a.y;
    }
    float inv = 1.0f / fmaxf((float)deg, 1.0f);
    u32 hi, lo;
    cvt2_split(acc.x * inv, acc.y * inv, hi, lo);
    g_mhi[(size_t)w * 32 + lane] = hi;
    g_mlo[(size_t)w * 32 + lane] = lo;
    if (lane == 0) g_cnt[w] = 0;          // re-arm for next replay
}

// ---------------- kernel 3: wmma GEMM (3xBF16 split, fused single k-loop) ----
// BM=64 rows/block, 128 threads (4 warps), warp tile 32x64 (2x4 fragments).
// Single k-loop loads af_hi/af_lo/bf_hi/bf_lo once per k0 (12 fragment loads)
// and issues all 24 MMAs (hi*hi + hi*lo + lo*hi) -> 33% fewer shared loads and
// denser tensor issue than the 3-pass form. No reg cap (2 CTAs/SM, RF-limited).
// Epilogue: bias as accumulator fragments, bias+relu in regs, direct store.
#define BM 64
#define ASTRIDE 136
#define A_ELEMS (BM * ASTRIDE)                // 8704 bf16 (17408 B)
#define B_ELEMS (128 * ASTRIDE)               // 17408 bf16 (34816 B)
#define BIAS_OFF (2 * A_ELEMS + 2 * B_ELEMS)  // bf16-element offset of bias block
#define SMEM_DYN (BIAS_OFF * 2 + 16 * HH * 4) // 104448 + 8192 = 112640 bytes

__global__ __launch_bounds__(128)
void gemm_kernel(const int* __restrict__ nodes,
                 const float* __restrict__ bias,
                 float* __restrict__ out,
                 int n_rows) {
    extern __shared__ __nv_bfloat16 smem[];
    __nv_bfloat16* Ahi = smem;
    __nv_bfloat16* Alo = smem + A_ELEMS;
    __nv_bfloat16* Bhi = smem + 2 * A_ELEMS;
    __nv_bfloat16* Blo = smem + 2 * A_ELEMS + B_ELEMS;
    float* biasf = (float*)(smem + BIAS_OFF);   // 16 rows x 128 cols replicated

    int tid = threadIdx.x;
    int wid = tid >> 5;
    int lane = tid & 31;
    int block_m = blockIdx.x * BM;

    // ---- stage B = W hi & lo, col-major: Bs[k + h*ASTRIDE] ----
    {
        const uint4* shi = (const uint4*)g_Whi;
        const uint4* slo = (const uint4*)g_Wlo;
        #pragma unroll
        for (int i = 0; i < (HH * KK / 8) / 128; ++i) {
            int idx = tid + i * 128;          // octet index
            int h = idx >> 4;                 // 16 octets per h
            int k = (idx & 15) * 8;
            *(uint4*)&Bhi[k + h * ASTRIDE] = shi[idx];
            *(uint4*)&Blo[k + h * ASTRIDE] = slo[idx];
        }
    }

    // ---- stage A tiles: pure uint4 copies of pre-split data ----
    // 2 threads per row: half 0 = self feats, half 1 = neigh mean
    {
        int r = tid >> 1;
        int half = tid & 1;
        int row = block_m + r;
        bool valid = row < n_rows;
        int g = valid ? nodes[row] : 0;
        const uint4* shi = (const uint4*)(half ? &g_mhi[(size_t)g * 32]
                                               : &g_fhi[(size_t)g * 32]);
        const uint4* slo = (const uint4*)(half ? &g_mlo[(size_t)g * 32]
                                               : &g_flo[(size_t)g * 32]);
        uint4 z = make_uint4(0, 0, 0, 0);
        #pragma unroll
        for (int q = 0; q < 8; ++q) {
            *(uint4*)&Ahi[r * ASTRIDE + half * 64 + q * 8] = valid ? shi[q] : z;
            *(uint4*)&Alo[r * ASTRIDE + half * 64 + q * 8] = valid ? slo[q] : z;
        }
    }

    // ---- fill replicated bias block (16 identical rows) ----
    #pragma unroll
    for (int i = 0; i < 16; ++i) {
        int idx = tid + i * 128;              // 2048 entries
        biasf[idx] = bias[idx & (HH - 1)];
    }
    __syncthreads();

    // ---- wmma: 4 warps in 2x2 grid, warp tile 32x64 (2x4 frags) ----
    int wm = wid & 1;      // rows wm*32
    int wn = wid >> 1;     // cols wn*64

    wmma::fragment<wmma::accumulator, 16, 16, 16, float> acc[2][4];
    #pragma unroll
    for (int i = 0; i < 2; ++i)
        #pragma unroll
        for (int j = 0; j < 4; ++j) wmma::fill_fragment(acc[i][j], 0.0f);

    // fused single k-loop: load hi+lo fragments once, issue all 3 products
    #pragma unroll
    for (int k0 = 0; k0 < KK; k0 += 16) {
        wmma::fragment<wmma::matrix_a, 16, 16, 16, __nv_bfloat16, wmma::row_major> af_hi[2], af_lo[2];
        wmma::fragment<wmma::matrix_b, 16, 16, 16, __nv_bfloat16, wmma::col_major> bf_hi[4], bf_lo[4];
        #pragma unroll
        for (int i = 0; i < 2; ++i) {
            wmma::load_matrix_sync(af_hi[i], Ahi + (wm * 32 + i * 16) * ASTRIDE + k0, ASTRIDE);
            wmma::load_matrix_sync(af_lo[i], Alo + (wm * 32 + i * 16) * ASTRIDE + k0, ASTRIDE);
        }
        #pragma unroll
        for (int j = 0; j < 4; ++j) {
            wmma::load_matrix_sync(bf_hi[j], Bhi + k0 + (wn * 64 + j * 16) * ASTRIDE, ASTRIDE);
            wmma::load_matrix_sync(bf_lo[j], Blo + k0 + (wn * 64 + j * 16) * ASTRIDE, ASTRIDE);
        }
        #pragma unroll
        for (int i = 0; i < 2; ++i)
            #pragma unroll
            for (int j = 0; j < 4; ++j)
                wmma::mma_sync(acc[i][j], af_hi[i], bf_hi[j], acc[i][j]);
        #pragma unroll
        for (int i = 0; i < 2; ++i)
            #pragma unroll
            for (int j = 0; j < 4; ++j)
                wmma::mma_sync(acc[i][j], af_hi[i], bf_lo[j], acc[i][j]);
        #pragma unroll
        for (int i = 0; i < 2; ++i)
            #pragma unroll
            for (int j = 0; j < 4; ++j)
                wmma::mma_sync(acc[i][j], af_lo[i], bf_hi[j], acc[i][j]);
    }

    // ---- epilogue ----
    if (block_m + BM <= n_rows) {
        // full tile: bias+relu in registers, direct fragment store to gmem
        wmma::fragment<wmma::accumulator, 16, 16, 16, float> bfr[4];
        #pragma unroll
        for (int j = 0; j < 4; ++j)
            wmma::load_matrix_sync(bfr[j], biasf + wn * 64 + j * 16, HH,
                                   wmma::mem_row_major);
        #pragma unroll
        for (int i = 0; i < 2; ++i)
            #pragma unroll
            for (int j = 0; j < 4; ++j) {
                #pragma unroll
                for (int t = 0; t < acc[i][j].num_elements; ++t)
                    acc[i][j].x[t] = fmaxf(acc[i][j].x[t] + bfr[j].x[t], 0.f);
                wmma::store_matrix_sync(
                    out + (size_t)(block_m + wm * 32 + i * 16) * HH + wn * 64 + j * 16,
                    acc[i][j], HH, wmma::mem_row_major);
            }
    } else {
        // partial tail block: stage through smem with per-row guards
        __syncthreads();   // tiles no longer needed
        float* stage = (float*)smem;                   // 4 warps x 32x64 f32 = 32KB
        float* wstage = stage + wid * (32 * 64);
        #pragma unroll
        for (int i = 0; i < 2; ++i)
            #pragma unroll
            for (int j = 0; j < 4; ++j)
                wmma::store_matrix_sync(wstage + i * 16 * 64 + j * 16, acc[i][j],
                                        64, wmma::mem_row_major);
        __syncwarp();
        int row = block_m + wm * 32 + lane;
        if (row < n_rows) {
            const float* srow = wstage + lane * 64;
            float* orow = out + (size_t)row * HH + wn * 64;
            #pragma unroll
            for (int c = 0; c < 64; c += 4) {
                float4 o;
                o.x = fmaxf(srow[c + 0] + bias[wn * 64 + c + 0], 0.f);
                o.y = fmaxf(srow[c + 1] + bias[wn * 64 + c + 1], 0.f);
                o.z = fmaxf(srow[c + 2] + bias[wn * 64 + c + 2], 0.f);
                o.w = fmaxf(srow[c + 3] + bias[wn * 64 + c + 3], 0.f);
                *(float4*)&orow[c] = o;
            }
        }
    }
}

// ---------------- launch ----------------
extern "C" void kernel_launch(void* const* d_in, const int* in_sizes, int n_in,
                              void* d_out, int out_size) {
    const int*    nodes    = (const int*)d_in[0];
    const float*  features = (const float*)d_in[1];
    const int*    ei       = (const int*)d_in[2];
    const float*  W        = (const float*)d_in[3];
    const float*  bias     = (const float*)d_in[4];
    float*        out      = (float*)d_out;

    int n_rows  = in_sizes[0];           // B == N
    int n_nodes = in_sizes[1] / DD;      // N
    int n_edges = in_sizes[2] / 2;       // E

    const float2* feat2 = (const float2*)features;

    // opt-in to >48KB dynamic smem (immediate host-side call, idempotent)
    cudaFuncSetAttribute(gemm_kernel,
                         cudaFuncAttributeMaxDynamicSharedMemorySize, SMEM_DYN);

    // 1. fused: ELL fill (blocks [0,fb)) + split W/features (remaining blocks)
    {
        int fb = (n_edges + 255) / 256;
        int pb = (n_nodes * 32 + 255) / 256;
        k_fillprep<<<fb + pb, 256>>>(ei, feat2, W, n_edges, n_nodes, fb);
    }
    // 2. gather-reduce (writes split means, re-arms g_cnt)
    k_gather<<<(n_nodes * 32 + 255) / 256, 256>>>(feat2, n_nodes);
    // 3. wmma GEMM (fused 3-in-1 k-loop)
    {
        int blocks = (n_rows + BM - 1) / BM;
        gemm_kernel<<<blocks, 128, SMEM_DYN>>>(nodes, bias, out, n_rows);
    }
}